// round 1
// baseline (speedup 1.0000x reference)
#include <cuda_runtime.h>

#define N_NODES 20000
#define N_EDGES 320000
#define DIM_D   768
#define DIM_H   1024
#define SDIM    2000

// ---- scratch (static __device__ globals; no allocation in kernel_launch) ----
__device__ float g_v[DIM_D];     // W1 @ W2
__device__ float g_s1;           // b1 . W2
__device__ float g_z[N_NODES];   // x @ v
__device__ float g_deg[N_NODES];
__device__ float g_dinv[N_NODES];
__device__ float g_u[N_NODES];   // A z
__device__ float g_att[N_NODES]; // A (A z + s1) + b2
__device__ float g_cutoff;

// ---------------------------------------------------------------------------
// v[d] = sum_h W1[d,h] * W2[h];  block DIM_D computes s1 = b1 . W2
__global__ void k_v(const float* __restrict__ W1, const float* __restrict__ W2,
                    const float* __restrict__ b1) {
    int d = blockIdx.x;
    const float* rowp = (d < DIM_D) ? (W1 + (size_t)d * DIM_H) : b1;
    float s = 0.f;
    for (int h = threadIdx.x; h < DIM_H; h += blockDim.x)
        s += rowp[h] * W2[h];
    #pragma unroll
    for (int o = 16; o; o >>= 1) s += __shfl_xor_sync(0xffffffffu, s, o);
    __shared__ float red[8];
    int warp = threadIdx.x >> 5, lane = threadIdx.x & 31;
    if (!lane) red[warp] = s;
    __syncthreads();
    if (threadIdx.x == 0) {
        float t = 0.f;
        #pragma unroll
        for (int w = 0; w < 8; w++) t += red[w];
        if (d < DIM_D) g_v[d] = t; else g_s1 = t;
    }
}

// ---------------------------------------------------------------------------
// z[n] = x[n,:] . v  (one warp per node, float4 coalesced); also init deg = 1
__global__ void k_z(const float* __restrict__ x) {
    __shared__ float sv[DIM_D];
    for (int i = threadIdx.x; i < DIM_D; i += blockDim.x) sv[i] = g_v[i];
    __syncthreads();
    int warp = threadIdx.x >> 5, lane = threadIdx.x & 31;
    int n = blockIdx.x * (blockDim.x >> 5) + warp;
    if (n >= N_NODES) return;
    const float4* xr = (const float4*)(x + (size_t)n * DIM_D);
    const float4* vv = (const float4*)sv;
    float sum = 0.f;
    #pragma unroll
    for (int i = lane; i < DIM_D / 4; i += 32) {
        float4 a = xr[i];
        float4 b = vv[i];
        sum += a.x * b.x + a.y * b.y + a.z * b.z + a.w * b.w;
    }
    #pragma unroll
    for (int o = 16; o; o >>= 1) sum += __shfl_xor_sync(0xffffffffu, sum, o);
    if (!lane) { g_z[n] = sum; g_deg[n] = 1.0f; }  // self-loop weight
}

// ---------------------------------------------------------------------------
__global__ void k_deg(const int* __restrict__ col, const float* __restrict__ ew) {
    int e = blockIdx.x * blockDim.x + threadIdx.x;
    if (e < N_EDGES) atomicAdd(&g_deg[col[e]], ew[e]);
}

// dinv = deg^-0.5; also seed u with self-loop term of first A-apply
__global__ void k_dinv() {
    int n = blockIdx.x * blockDim.x + threadIdx.x;
    if (n >= N_NODES) return;
    float di = 1.0f / sqrtf(g_deg[n]);
    g_dinv[n] = di;
    g_u[n] = di * di * g_z[n];
}

// u[c] += dinv[r]*w*dinv[c] * z[r]
__global__ void k_edge1(const int* __restrict__ row, const int* __restrict__ col,
                        const float* __restrict__ ew) {
    int e = blockIdx.x * blockDim.x + threadIdx.x;
    if (e >= N_EDGES) return;
    int r = row[e], c = col[e];
    atomicAdd(&g_u[c], g_dinv[r] * ew[e] * g_dinv[c] * g_z[r]);
}

// att[n] seeded with self-loop term of second A-apply (+ b2)
__global__ void k_att_init(const float* __restrict__ b2) {
    int n = blockIdx.x * blockDim.x + threadIdx.x;
    if (n >= N_NODES) return;
    float di = g_dinv[n];
    g_att[n] = di * di * (g_u[n] + g_s1) + b2[0];
}

// att[c] += dinv[r]*w*dinv[c] * (u[r] + s1)
__global__ void k_edge2(const int* __restrict__ row, const int* __restrict__ col,
                        const float* __restrict__ ew) {
    int e = blockIdx.x * blockDim.x + threadIdx.x;
    if (e >= N_EDGES) return;
    int r = row[e], c = col[e];
    atomicAdd(&g_att[c], g_dinv[r] * ew[e] * g_dinv[c] * (g_u[r] + g_s1));
}

// ---------------------------------------------------------------------------
// Single block: k = max(count(y>=0),1); cutoff = k-th largest of att[:S]
// (stable rank to match sorted_desc[k-1]); t from y; loss.
__global__ void k_select(const int* __restrict__ y, float* __restrict__ out,
                         int write_loss) {
    __shared__ float s_sent[SDIM];
    __shared__ float s_t[SDIM];
    __shared__ int   s_k;
    __shared__ float s_red[32];
    int tid = threadIdx.x;
    if (tid == 0) s_k = 0;
    for (int i = tid; i < SDIM; i += 1024) { s_sent[i] = g_att[i]; s_t[i] = 0.f; }
    __syncthreads();

    int kc = 0;
    for (int j = tid; j < SDIM; j += 1024) {
        int yy = y[j];
        if (yy >= 0) kc++;
        if (yy > 0) s_t[yy] = 1.0f;   // idempotent writes; races benign
    }
    #pragma unroll
    for (int o = 16; o; o >>= 1) kc += __shfl_xor_sync(0xffffffffu, kc, o);
    if ((tid & 31) == 0) atomicAdd(&s_k, kc);
    __syncthreads();
    int k = max(s_k, 1);

    // stable-rank selection: each thread owns elements tid and tid+1024
    int i0 = tid, i1 = tid + 1024;
    float v0 = s_sent[i0];
    float v1 = (i1 < SDIM) ? s_sent[i1] : 0.f;
    int c0 = 0, c1 = 0;
    for (int j = 0; j < SDIM; j++) {        // broadcast shared read per iter
        float sj = s_sent[j];
        c0 += (sj > v0) || (sj == v0 && j < i0);
        c1 += (sj > v1) || (sj == v1 && j < i1);
    }
    if (c0 == k - 1) g_cutoff = v0;
    if (i1 < SDIM && c1 == k - 1) g_cutoff = v1;

    // loss = -mean( t*logsig(sent) + (1-t)*logsig(-sent) )
    float acc = 0.f;
    for (int j = tid; j < SDIM; j += 1024) {
        float v = s_sent[j], t = s_t[j];
        float lp = log1pf(expf(-fabsf(v)));
        float l1 = fminf(v, 0.f) - lp;    // log_sigmoid(v)
        float l2 = fminf(-v, 0.f) - lp;   // log_sigmoid(-v)
        acc += t * l1 + (1.f - t) * l2;
    }
    #pragma unroll
    for (int o = 16; o; o >>= 1) acc += __shfl_xor_sync(0xffffffffu, acc, o);
    if ((tid & 31) == 0) s_red[tid >> 5] = acc;
    __syncthreads();
    if (tid == 0 && write_loss) {
        float tot = 0.f;
        #pragma unroll
        for (int w = 0; w < 32; w++) tot += s_red[w];
        out[0] = -tot / (float)SDIM;
    }
}

// ---------------------------------------------------------------------------
__global__ void k_mask(float* __restrict__ out, int off) {
    int n = blockIdx.x * blockDim.x + threadIdx.x;
    if (n < N_NODES) out[off + n] = (g_att[n] >= g_cutoff) ? 1.0f : 0.0f;
}

// ---------------------------------------------------------------------------
extern "C" void kernel_launch(void* const* d_in, const int* in_sizes, int n_in,
                              void* d_out, int out_size) {
    const float* x  = (const float*)d_in[0];
    const int*   ei = (const int*)d_in[1];
    const float* ew = (const float*)d_in[2];
    const int*   y  = (const int*)d_in[3];
    const float* W1 = (const float*)d_in[4];
    const float* b1 = (const float*)d_in[5];
    const float* W2 = (const float*)d_in[6];
    const float* b2 = (const float*)d_in[7];
    const int* row = ei;             // edge_index[0,:]
    const int* col = ei + N_EDGES;   // edge_index[1,:]
    float* out = (float*)d_out;
    int off = (out_size > N_NODES) ? (out_size - N_NODES) : 0;  // expect 1

    k_v<<<DIM_D + 1, 256>>>(W1, W2, b1);
    k_z<<<(N_NODES + 7) / 8, 256>>>(x);
    k_deg<<<(N_EDGES + 255) / 256, 256>>>(col, ew);
    k_dinv<<<(N_NODES + 255) / 256, 256>>>();
    k_edge1<<<(N_EDGES + 255) / 256, 256>>>(row, col, ew);
    k_att_init<<<(N_NODES + 255) / 256, 256>>>(b2);
    k_edge2<<<(N_EDGES + 255) / 256, 256>>>(row, col, ew);
    k_select<<<1, 1024>>>(y, out, off >= 1 ? 1 : 0);
    k_mask<<<(N_NODES + 255) / 256, 256>>>(out, off);
}

// round 2
// speedup vs baseline: 3.5891x; 3.5891x over previous
#include <cuda_runtime.h>

#define N_NODES 20000
#define N_EDGES 320000
#define DIM_D   768
#define DIM_H   1024
#define SDIM    2000
#define VB      (DIM_D + 1)              // blocks for v/s1 computation
#define E4      (N_EDGES / 4)            // 80000 edge-quads
#define EB4     ((E4 + 255) / 256)       // 313 blocks

// ---- scratch (static __device__ globals; no allocation in kernel_launch) ----
__device__ float g_v[DIM_D];     // W1 @ W2
__device__ float g_s1;           // b1 . W2
__device__ float g_z[N_NODES];   // x @ v
__device__ float g_deg[N_NODES]; // edge-weight in-degree (zeroed; +1 self loop at use)
__device__ float g_dinv[N_NODES];
__device__ float g_u[N_NODES];   // A z  (seeded with self-loop term)
__device__ float g_att2[N_NODES];// edge contribution of second A-apply (zeroed)
__device__ float g_nw[N_EDGES];  // cached normalized edge weight
__device__ float g_att_s[SDIM];  // att[0:S) exactly as k_select saw them
__device__ float g_cutoff;

// ---------------------------------------------------------------------------
// Merged: blocks [0,VB): v[d] = W1[d,:].W2 (block DIM_D: s1 = b1.W2)
//         blocks [VB, VB+EB4): deg scatter over 4 edges/thread
__global__ void k_vdeg(const float* __restrict__ W1, const float* __restrict__ W2,
                       const float* __restrict__ b1,
                       const int* __restrict__ col, const float* __restrict__ ew) {
    if (blockIdx.x < VB) {
        int d = blockIdx.x;
        const float* rowp = (d < DIM_D) ? (W1 + (size_t)d * DIM_H) : b1;
        float s = 0.f;
        for (int h = threadIdx.x; h < DIM_H; h += 256)
            s += rowp[h] * W2[h];
        #pragma unroll
        for (int o = 16; o; o >>= 1) s += __shfl_xor_sync(0xffffffffu, s, o);
        __shared__ float red[8];
        int warp = threadIdx.x >> 5, lane = threadIdx.x & 31;
        if (!lane) red[warp] = s;
        __syncthreads();
        if (threadIdx.x == 0) {
            float t = 0.f;
            #pragma unroll
            for (int w = 0; w < 8; w++) t += red[w];
            if (d < DIM_D) g_v[d] = t; else g_s1 = t;
        }
    } else {
        int i = (blockIdx.x - VB) * 256 + threadIdx.x;
        if (i < E4) {
            int4   c = ((const int4*)col)[i];
            float4 w = ((const float4*)ew)[i];
            atomicAdd(&g_deg[c.x], w.x);
            atomicAdd(&g_deg[c.y], w.y);
            atomicAdd(&g_deg[c.z], w.z);
            atomicAdd(&g_deg[c.w], w.w);
        }
    }
}

// ---------------------------------------------------------------------------
// z[n] = x[n,:] . v  (one warp per node, float4 coalesced)
__global__ void k_z(const float* __restrict__ x) {
    __shared__ float sv[DIM_D];
    for (int i = threadIdx.x; i < DIM_D; i += blockDim.x) sv[i] = g_v[i];
    __syncthreads();
    int warp = threadIdx.x >> 5, lane = threadIdx.x & 31;
    int n = blockIdx.x * (blockDim.x >> 5) + warp;
    if (n >= N_NODES) return;
    const float4* xr = (const float4*)(x + (size_t)n * DIM_D);
    const float4* vv = (const float4*)sv;
    float sum = 0.f;
    #pragma unroll
    for (int i = lane; i < DIM_D / 4; i += 32) {
        float4 a = xr[i];
        float4 b = vv[i];
        sum += a.x * b.x + a.y * b.y + a.z * b.z + a.w * b.w;
    }
    #pragma unroll
    for (int o = 16; o; o >>= 1) sum += __shfl_xor_sync(0xffffffffu, sum, o);
    if (!lane) g_z[n] = sum;
}

// ---------------------------------------------------------------------------
// dinv = (deg+1)^-0.5; seed u with self-loop term
__global__ void k_dinv() {
    int n = blockIdx.x * blockDim.x + threadIdx.x;
    if (n >= N_NODES) return;
    float di = 1.0f / sqrtf(g_deg[n] + 1.0f);
    g_dinv[n] = di;
    g_u[n] = di * di * g_z[n];
}

// ---------------------------------------------------------------------------
// nw[e] = dinv[r]*w*dinv[c];  u[c] += nw*z[r]   (4 edges/thread)
__global__ void k_edge1(const int* __restrict__ row, const int* __restrict__ col,
                        const float* __restrict__ ew) {
    int i = blockIdx.x * blockDim.x + threadIdx.x;
    if (i >= E4) return;
    int4   r = ((const int4*)row)[i];
    int4   c = ((const int4*)col)[i];
    float4 w = ((const float4*)ew)[i];
    float4 nw;
    nw.x = g_dinv[r.x] * w.x * g_dinv[c.x];
    nw.y = g_dinv[r.y] * w.y * g_dinv[c.y];
    nw.z = g_dinv[r.z] * w.z * g_dinv[c.z];
    nw.w = g_dinv[r.w] * w.w * g_dinv[c.w];
    ((float4*)g_nw)[i] = nw;
    atomicAdd(&g_u[c.x], nw.x * g_z[r.x]);
    atomicAdd(&g_u[c.y], nw.y * g_z[r.y]);
    atomicAdd(&g_u[c.z], nw.z * g_z[r.z]);
    atomicAdd(&g_u[c.w], nw.w * g_z[r.w]);
}

// ---------------------------------------------------------------------------
// att2[c] += nw * (u[r] + s1)   (4 edges/thread)
__global__ void k_edge2(const int* __restrict__ row, const int* __restrict__ col) {
    int i = blockIdx.x * blockDim.x + threadIdx.x;
    if (i >= E4) return;
    float s1 = g_s1;
    int4   r  = ((const int4*)row)[i];
    int4   c  = ((const int4*)col)[i];
    float4 nw = ((const float4*)g_nw)[i];
    atomicAdd(&g_att2[c.x], nw.x * (g_u[r.x] + s1));
    atomicAdd(&g_att2[c.y], nw.y * (g_u[r.y] + s1));
    atomicAdd(&g_att2[c.z], nw.z * (g_u[r.z] + s1));
    atomicAdd(&g_att2[c.w], nw.w * (g_u[r.w] + s1));
}

// ---------------------------------------------------------------------------
// Single block: att[0:S), k, cutoff via k iterative argmax, loss.
__global__ void k_select(const int* __restrict__ y, const float* __restrict__ b2,
                         float* __restrict__ out, int write_loss) {
    __shared__ float s_val[SDIM];
    __shared__ float s_t[SDIM];
    __shared__ int   s_k;
    __shared__ float s_rv[32];
    __shared__ int   s_ri[32];
    __shared__ float s_cut;
    int tid = threadIdx.x;
    if (tid == 0) s_k = 0;
    float bb = b2[0];
    float s1 = g_s1;
    for (int i = tid; i < SDIM; i += 1024) {
        float di = g_dinv[i];
        float a = di * di * (g_u[i] + s1) + bb + g_att2[i];
        s_val[i] = a;
        g_att_s[i] = a;           // exact bits reused by k_mask
        s_t[i] = 0.f;
    }
    __syncthreads();

    int kc = 0;
    for (int j = tid; j < SDIM; j += 1024) {
        int yy = y[j];
        kc += (yy >= 0);
        if (yy > 0) s_t[yy] = 1.0f;   // idempotent; races benign
    }
    #pragma unroll
    for (int o = 16; o; o >>= 1) kc += __shfl_xor_sync(0xffffffffu, kc, o);
    if ((tid & 31) == 0) atomicAdd(&s_k, kc);
    __syncthreads();
    int k = max(s_k, 1);

    // per-thread loss accumulation BEFORE destructive selection
    float acc = 0.f;
    for (int j = tid; j < SDIM; j += 1024) {
        float v = s_val[j], t = s_t[j];
        float lp = log1pf(expf(-fabsf(v)));
        acc += t * (fminf(v, 0.f) - lp) + (1.f - t) * (fminf(-v, 0.f) - lp);
    }

    // k iterative (val, idx) argmax reductions; remove one instance each round
    for (int it = 0; it < k; it++) {
        float bv = -3.4e38f;
        int   bi = SDIM;
        for (int j = tid; j < SDIM; j += 1024) {
            float v = s_val[j];
            if (v > bv) { bv = v; bi = j; }     // strided ascending j -> first occurrence kept
        }
        #pragma unroll
        for (int o = 16; o; o >>= 1) {
            float ov = __shfl_xor_sync(0xffffffffu, bv, o);
            int   oi = __shfl_xor_sync(0xffffffffu, bi, o);
            if (ov > bv || (ov == bv && oi < bi)) { bv = ov; bi = oi; }
        }
        if ((tid & 31) == 0) { s_rv[tid >> 5] = bv; s_ri[tid >> 5] = bi; }
        __syncthreads();
        if (tid < 32) {
            bv = s_rv[tid]; bi = s_ri[tid];
            #pragma unroll
            for (int o = 16; o; o >>= 1) {
                float ov = __shfl_xor_sync(0xffffffffu, bv, o);
                int   oi = __shfl_xor_sync(0xffffffffu, bi, o);
                if (ov > bv || (ov == bv && oi < bi)) { bv = ov; bi = oi; }
            }
            if (tid == 0) { s_cut = bv; s_val[bi] = -3.4e38f; }
        }
        __syncthreads();
    }
    if (tid == 0) g_cutoff = s_cut;

    // loss reduction
    #pragma unroll
    for (int o = 16; o; o >>= 1) acc += __shfl_xor_sync(0xffffffffu, acc, o);
    if ((tid & 31) == 0) s_rv[tid >> 5] = acc;
    __syncthreads();
    if (tid == 0 && write_loss) {
        float tot = 0.f;
        #pragma unroll
        for (int w = 0; w < 32; w++) tot += s_rv[w];
        out[0] = -tot / (float)SDIM;
    }
}

// ---------------------------------------------------------------------------
__global__ void k_mask(const float* __restrict__ b2, float* __restrict__ out, int off) {
    int n = blockIdx.x * blockDim.x + threadIdx.x;
    if (n >= N_NODES) return;
    float a;
    if (n < SDIM) {
        a = g_att_s[n];                      // identical bits to k_select
    } else {
        float di = g_dinv[n];
        a = di * di * (g_u[n] + g_s1) + b2[0] + g_att2[n];
    }
    out[off + n] = (a >= g_cutoff) ? 1.0f : 0.0f;
}

// ---------------------------------------------------------------------------
extern "C" void kernel_launch(void* const* d_in, const int* in_sizes, int n_in,
                              void* d_out, int out_size) {
    const float* x  = (const float*)d_in[0];
    const int*   ei = (const int*)d_in[1];
    const float* ew = (const float*)d_in[2];
    const int*   y  = (const int*)d_in[3];
    const float* W1 = (const float*)d_in[4];
    const float* b1 = (const float*)d_in[5];
    const float* W2 = (const float*)d_in[6];
    const float* b2 = (const float*)d_in[7];
    const int* row = ei;             // edge_index[0,:]
    const int* col = ei + N_EDGES;   // edge_index[1,:]
    float* out = (float*)d_out;
    int off = (out_size > N_NODES) ? (out_size - N_NODES) : 0;  // expect 1

    void* d_deg = 0; void* d_att2 = 0;
    cudaGetSymbolAddress(&d_deg,  g_deg);
    cudaGetSymbolAddress(&d_att2, g_att2);
    cudaMemsetAsync(d_deg,  0, N_NODES * sizeof(float));
    cudaMemsetAsync(d_att2, 0, N_NODES * sizeof(float));

    k_vdeg<<<VB + EB4, 256>>>(W1, W2, b1, col, ew);
    k_z<<<(N_NODES + 7) / 8, 256>>>(x);
    k_dinv<<<(N_NODES + 255) / 256, 256>>>();
    k_edge1<<<EB4, 256>>>(row, col, ew);
    k_edge2<<<EB4, 256>>>(row, col);
    k_select<<<1, 1024>>>(y, b2, out, off >= 1 ? 1 : 0);
    k_mask<<<(N_NODES + 255) / 256, 256>>>(b2, out, off);
}

// round 3
// speedup vs baseline: 3.7599x; 1.0476x over previous
#include <cuda_runtime.h>

#define N_NODES 20000
#define N_EDGES 320000
#define DIM_D   768
#define DIM_H   1024
#define SDIM    2000
#define VB      (DIM_D + 1)              // blocks for v/s1 computation
#define E4      (N_EDGES / 4)            // 80000 edge-quads (deg pass)
#define EB4     ((E4 + 255) / 256)       // 313 blocks
#define EB1     ((N_EDGES + 255) / 256)  // 1250 blocks (1 edge/thread)
#define NB      ((N_NODES + 255) / 256)

// ---- scratch (static __device__ globals; no allocation in kernel_launch) ----
__device__ float g_v[DIM_D];     // W1 @ W2
__device__ float g_s1;           // b1 . W2
__device__ float g_deg[N_NODES]; // edge-weight in-degree (memset 0; +1 self loop)
__device__ float g_dinv[N_NODES];
__device__ float g_q[N_NODES];   // dinv * z
__device__ float g_p[N_NODES];   // edge accum pass 1 (zeroed in k_dinv)
__device__ float g_q2[N_NODES];  // dinv * (u + s1)
__device__ float g_p2[N_NODES];  // edge accum pass 2 (zeroed in k_dinv)
__device__ float g_att_s[SDIM];  // att[0:S) exactly as k_select saw them
__device__ float g_cutoff;

// ---------------------------------------------------------------------------
// Merged: blocks [0,VB): v[d] = W1[d,:].W2 (block DIM_D: s1 = b1.W2)
//         blocks [VB, VB+EB4): deg scatter, 4 edges/thread
__global__ void k_vdeg(const float* __restrict__ W1, const float* __restrict__ W2,
                       const float* __restrict__ b1,
                       const int* __restrict__ col, const float* __restrict__ ew) {
    if (blockIdx.x < VB) {
        int d = blockIdx.x;
        const float* rowp = (d < DIM_D) ? (W1 + (size_t)d * DIM_H) : b1;
        float s = 0.f;
        for (int h = threadIdx.x; h < DIM_H; h += 256)
            s += rowp[h] * W2[h];
        #pragma unroll
        for (int o = 16; o; o >>= 1) s += __shfl_xor_sync(0xffffffffu, s, o);
        __shared__ float red[8];
        int warp = threadIdx.x >> 5, lane = threadIdx.x & 31;
        if (!lane) red[warp] = s;
        __syncthreads();
        if (threadIdx.x == 0) {
            float t = 0.f;
            #pragma unroll
            for (int w = 0; w < 8; w++) t += red[w];
            if (d < DIM_D) g_v[d] = t; else g_s1 = t;
        }
    } else {
        int i = (blockIdx.x - VB) * 256 + threadIdx.x;
        if (i < E4) {
            int4   c = ((const int4*)col)[i];
            float4 w = ((const float4*)ew)[i];
            atomicAdd(&g_deg[c.x], w.x);
            atomicAdd(&g_deg[c.y], w.y);
            atomicAdd(&g_deg[c.z], w.z);
            atomicAdd(&g_deg[c.w], w.w);
        }
    }
}

// ---------------------------------------------------------------------------
// dinv = (deg+1)^-0.5; zero the two edge accumulators
__global__ void k_dinv() {
    int n = blockIdx.x * blockDim.x + threadIdx.x;
    if (n >= N_NODES) return;
    g_dinv[n] = rsqrtf(g_deg[n] + 1.0f);
    g_p[n] = 0.f;
    g_p2[n] = 0.f;
}

// ---------------------------------------------------------------------------
// q[n] = dinv[n] * (x[n,:] . v)   (one warp per node, float4 coalesced)
__global__ void k_z(const float* __restrict__ x) {
    __shared__ float sv[DIM_D];
    for (int i = threadIdx.x; i < DIM_D; i += blockDim.x) sv[i] = g_v[i];
    __syncthreads();
    int warp = threadIdx.x >> 5, lane = threadIdx.x & 31;
    int n = blockIdx.x * (blockDim.x >> 5) + warp;
    if (n >= N_NODES) return;
    const float4* xr = (const float4*)(x + (size_t)n * DIM_D);
    const float4* vv = (const float4*)sv;
    float sum = 0.f;
    #pragma unroll
    for (int i = lane; i < DIM_D / 4; i += 32) {
        float4 a = xr[i];
        float4 b = vv[i];
        sum += a.x * b.x + a.y * b.y + a.z * b.z + a.w * b.w;
    }
    #pragma unroll
    for (int o = 16; o; o >>= 1) sum += __shfl_xor_sync(0xffffffffu, sum, o);
    if (!lane) g_q[n] = g_dinv[n] * sum;
}

// ---------------------------------------------------------------------------
// p[c] += w * q[r]   (1 edge/thread; full-chip occupancy)
__global__ void k_edge1(const int* __restrict__ row, const int* __restrict__ col,
                        const float* __restrict__ ew) {
    int e = blockIdx.x * blockDim.x + threadIdx.x;
    if (e >= N_EDGES) return;
    atomicAdd(&g_p[col[e]], ew[e] * g_q[row[e]]);
}

// ---------------------------------------------------------------------------
// q2[n] = dinv * (u + s1),  u = dinv * (p + q)
__global__ void k_mid() {
    int n = blockIdx.x * blockDim.x + threadIdx.x;
    if (n >= N_NODES) return;
    float di = g_dinv[n];
    g_q2[n] = di * (di * (g_p[n] + g_q[n]) + g_s1);
}

// ---------------------------------------------------------------------------
// p2[c] += w * q2[r]
__global__ void k_edge2(const int* __restrict__ row, const int* __restrict__ col,
                        const float* __restrict__ ew) {
    int e = blockIdx.x * blockDim.x + threadIdx.x;
    if (e >= N_EDGES) return;
    atomicAdd(&g_p2[col[e]], ew[e] * g_q2[row[e]]);
}

// ---------------------------------------------------------------------------
// att[n] = dinv[n]*(p2[n] + q2[n]) + b2
// Single block: k = count(y>=0); cutoff = k-th largest of att[:S]; loss.
__global__ void k_select(const int* __restrict__ y, const float* __restrict__ b2,
                         float* __restrict__ out, int write_loss) {
    __shared__ float s_val[SDIM];
    __shared__ float s_t[SDIM];
    __shared__ int   s_k;
    __shared__ float s_rv[32];
    __shared__ int   s_ri[32];
    __shared__ float s_cut;
    int tid = threadIdx.x;
    if (tid == 0) s_k = 0;
    float bb = b2[0];
    for (int i = tid; i < SDIM; i += 1024) {
        float a = g_dinv[i] * (g_p2[i] + g_q2[i]) + bb;
        s_val[i] = a;
        g_att_s[i] = a;           // exact bits reused by k_mask
        s_t[i] = 0.f;
    }
    __syncthreads();

    int kc = 0;
    for (int j = tid; j < SDIM; j += 1024) {
        int yy = y[j];
        kc += (yy >= 0);
        if (yy > 0) s_t[yy] = 1.0f;   // idempotent; races benign
    }
    #pragma unroll
    for (int o = 16; o; o >>= 1) kc += __shfl_xor_sync(0xffffffffu, kc, o);
    if ((tid & 31) == 0) atomicAdd(&s_k, kc);
    __syncthreads();
    int k = max(s_k, 1);

    // per-thread loss accumulation BEFORE destructive selection
    float acc = 0.f;
    for (int j = tid; j < SDIM; j += 1024) {
        float v = s_val[j], t = s_t[j];
        float lp = log1pf(expf(-fabsf(v)));
        acc += t * (fminf(v, 0.f) - lp) + (1.f - t) * (fminf(-v, 0.f) - lp);
    }

    // k iterative (val, idx) argmax reductions; remove one instance each round
    for (int it = 0; it < k; it++) {
        float bv = -3.4e38f;
        int   bi = SDIM;
        for (int j = tid; j < SDIM; j += 1024) {
            float v = s_val[j];
            if (v > bv) { bv = v; bi = j; }
        }
        #pragma unroll
        for (int o = 16; o; o >>= 1) {
            float ov = __shfl_xor_sync(0xffffffffu, bv, o);
            int   oi = __shfl_xor_sync(0xffffffffu, bi, o);
            if (ov > bv || (ov == bv && oi < bi)) { bv = ov; bi = oi; }
        }
        if ((tid & 31) == 0) { s_rv[tid >> 5] = bv; s_ri[tid >> 5] = bi; }
        __syncthreads();
        if (tid < 32) {
            bv = s_rv[tid]; bi = s_ri[tid];
            #pragma unroll
            for (int o = 16; o; o >>= 1) {
                float ov = __shfl_xor_sync(0xffffffffu, bv, o);
                int   oi = __shfl_xor_sync(0xffffffffu, bi, o);
                if (ov > bv || (ov == bv && oi < bi)) { bv = ov; bi = oi; }
            }
            if (tid == 0) { s_cut = bv; s_val[bi] = -3.4e38f; }
        }
        __syncthreads();
    }
    if (tid == 0) g_cutoff = s_cut;

    // loss reduction
    #pragma unroll
    for (int o = 16; o; o >>= 1) acc += __shfl_xor_sync(0xffffffffu, acc, o);
    if ((tid & 31) == 0) s_rv[tid >> 5] = acc;
    __syncthreads();
    if (tid == 0 && write_loss) {
        float tot = 0.f;
        #pragma unroll
        for (int w = 0; w < 32; w++) tot += s_rv[w];
        out[0] = -tot / (float)SDIM;
    }
}

// ---------------------------------------------------------------------------
__global__ void k_mask(const float* __restrict__ b2, float* __restrict__ out, int off) {
    int n = blockIdx.x * blockDim.x + threadIdx.x;
    if (n >= N_NODES) return;
    float a;
    if (n < SDIM) {
        a = g_att_s[n];                      // identical bits to k_select
    } else {
        a = g_dinv[n] * (g_p2[n] + g_q2[n]) + b2[0];
    }
    out[off + n] = (a >= g_cutoff) ? 1.0f : 0.0f;
}

// ---------------------------------------------------------------------------
extern "C" void kernel_launch(void* const* d_in, const int* in_sizes, int n_in,
                              void* d_out, int out_size) {
    const float* x  = (const float*)d_in[0];
    const int*   ei = (const int*)d_in[1];
    const float* ew = (const float*)d_in[2];
    const int*   y  = (const int*)d_in[3];
    const float* W1 = (const float*)d_in[4];
    const float* b1 = (const float*)d_in[5];
    const float* W2 = (const float*)d_in[6];
    const float* b2 = (const float*)d_in[7];
    const int* row = ei;             // edge_index[0,:]
    const int* col = ei + N_EDGES;   // edge_index[1,:]
    float* out = (float*)d_out;
    int off = (out_size > N_NODES) ? (out_size - N_NODES) : 0;  // expect 1

    void* d_deg = 0;
    cudaGetSymbolAddress(&d_deg, g_deg);
    cudaMemsetAsync(d_deg, 0, N_NODES * sizeof(float));

    k_vdeg<<<VB + EB4, 256>>>(W1, W2, b1, col, ew);
    k_dinv<<<NB, 256>>>();
    k_z<<<(N_NODES + 7) / 8, 256>>>(x);
    k_edge1<<<EB1, 256>>>(row, col, ew);
    k_mid<<<NB, 256>>>();
    k_edge2<<<EB1, 256>>>(row, col, ew);
    k_select<<<1, 1024>>>(y, b2, out, off >= 1 ? 1 : 0);
    k_mask<<<NB, 256>>>(b2, out, off);
}

// round 4
// speedup vs baseline: 3.9508x; 1.0508x over previous
#include <cuda_runtime.h>

#define N_NODES 20000
#define N_EDGES 320000
#define DIM_D   768
#define DIM_H   1024
#define SDIM    2000
#define VB      (DIM_D + 1)              // blocks for v/s1 computation
#define E4      (N_EDGES / 4)            // 80000 edge-quads (deg pass)
#define EB4     ((E4 + 255) / 256)       // 313 blocks
#define E2      (N_EDGES / 2)            // 160000 edge-pairs
#define EB2     ((E2 + 255) / 256)       // 625 blocks
#define NB      ((N_NODES + 255) / 256)

// ---- scratch (static __device__ globals; zero-initialized at module load) ----
__device__ float g_v[DIM_D];     // W1 @ W2
__device__ float g_s1;           // b1 . W2
__device__ float g_deg[N_NODES]; // edge-weight in-degree; re-zeroed by k_mask each run
__device__ float g_dinv[N_NODES];
__device__ float g_q[N_NODES];   // dinv * z
__device__ float g_p[N_NODES];   // edge accum pass 1 (zeroed in k_z)
__device__ float g_q2[N_NODES];  // dinv * (u + s1)
__device__ float g_p2[N_NODES];  // edge accum pass 2 (zeroed in k_z)
__device__ float g_att_s[SDIM];  // att[0:S) exactly as k_select saw them
__device__ float g_cutoff;

// ---------------------------------------------------------------------------
// Merged: blocks [0,VB): v[d] = W1[d,:].W2 (block DIM_D: s1 = b1.W2)
//         blocks [VB, VB+EB4): deg scatter, 4 edges/thread
__global__ void k_vdeg(const float* __restrict__ W1, const float* __restrict__ W2,
                       const float* __restrict__ b1,
                       const int* __restrict__ col, const float* __restrict__ ew) {
    if (blockIdx.x < VB) {
        int d = blockIdx.x;
        const float* rowp = (d < DIM_D) ? (W1 + (size_t)d * DIM_H) : b1;
        float s = 0.f;
        for (int h = threadIdx.x; h < DIM_H; h += 256)
            s += rowp[h] * W2[h];
        #pragma unroll
        for (int o = 16; o; o >>= 1) s += __shfl_xor_sync(0xffffffffu, s, o);
        __shared__ float red[8];
        int warp = threadIdx.x >> 5, lane = threadIdx.x & 31;
        if (!lane) red[warp] = s;
        __syncthreads();
        if (threadIdx.x == 0) {
            float t = 0.f;
            #pragma unroll
            for (int w = 0; w < 8; w++) t += red[w];
            if (d < DIM_D) g_v[d] = t; else g_s1 = t;
        }
    } else {
        int i = (blockIdx.x - VB) * 256 + threadIdx.x;
        if (i < E4) {
            int4   c = ((const int4*)col)[i];
            float4 w = ((const float4*)ew)[i];
            atomicAdd(&g_deg[c.x], w.x);
            atomicAdd(&g_deg[c.y], w.y);
            atomicAdd(&g_deg[c.z], w.z);
            atomicAdd(&g_deg[c.w], w.w);
        }
    }
}

// ---------------------------------------------------------------------------
// Per node (1 warp): dinv = rsqrt(deg+1); q = dinv * (x[n,:] . v)
// Side work: zero g_p / g_p2 before the edge passes.
// x read with streaming hint so col/ew stay L2-resident for k_edge1.
__global__ void k_z(const float* __restrict__ x) {
    __shared__ float sv[DIM_D];
    for (int i = threadIdx.x; i < DIM_D; i += blockDim.x) sv[i] = g_v[i];
    // zero accumulators (grid covers 2500 blocks; first NB*?: use global stride)
    for (int i = blockIdx.x * blockDim.x + threadIdx.x; i < N_NODES;
         i += gridDim.x * blockDim.x) {
        g_p[i] = 0.f;
        g_p2[i] = 0.f;
    }
    __syncthreads();
    int warp = threadIdx.x >> 5, lane = threadIdx.x & 31;
    int n = blockIdx.x * (blockDim.x >> 5) + warp;
    if (n >= N_NODES) return;
    const float4* xr = (const float4*)(x + (size_t)n * DIM_D);
    const float4* vv = (const float4*)sv;
    float sum = 0.f;
    #pragma unroll
    for (int i = lane; i < DIM_D / 4; i += 32) {
        float4 a = __ldcs(&xr[i]);      // streaming: don't pollute L2
        float4 b = vv[i];
        sum += a.x * b.x + a.y * b.y + a.z * b.z + a.w * b.w;
    }
    #pragma unroll
    for (int o = 16; o; o >>= 1) sum += __shfl_xor_sync(0xffffffffu, sum, o);
    if (!lane) {
        float di = rsqrtf(g_deg[n] + 1.0f);
        g_dinv[n] = di;
        g_q[n] = di * sum;
    }
}

// ---------------------------------------------------------------------------
// p[c] += w * q[r]   (2 edges/thread, vectorized index loads)
__global__ void k_edge1(const int* __restrict__ row, const int* __restrict__ col,
                        const float* __restrict__ ew) {
    int i = blockIdx.x * blockDim.x + threadIdx.x;
    if (i >= E2) return;
    int2   r = ((const int2*)row)[i];
    int2   c = ((const int2*)col)[i];
    float2 w = ((const float2*)ew)[i];
    float a = w.x * g_q[r.x];
    float b = w.y * g_q[r.y];
    atomicAdd(&g_p[c.x], a);
    atomicAdd(&g_p[c.y], b);
}

// ---------------------------------------------------------------------------
// q2[n] = dinv * (u + s1),  u = dinv * (p + q)
__global__ void k_mid() {
    int n = blockIdx.x * blockDim.x + threadIdx.x;
    if (n >= N_NODES) return;
    float di = g_dinv[n];
    g_q2[n] = di * (di * (g_p[n] + g_q[n]) + g_s1);
}

// ---------------------------------------------------------------------------
// p2[c] += w * q2[r]   (2 edges/thread)
__global__ void k_edge2(const int* __restrict__ row, const int* __restrict__ col,
                        const float* __restrict__ ew) {
    int i = blockIdx.x * blockDim.x + threadIdx.x;
    if (i >= E2) return;
    int2   r = ((const int2*)row)[i];
    int2   c = ((const int2*)col)[i];
    float2 w = ((const float2*)ew)[i];
    float a = w.x * g_q2[r.x];
    float b = w.y * g_q2[r.y];
    atomicAdd(&g_p2[c.x], a);
    atomicAdd(&g_p2[c.y], b);
}

// ---------------------------------------------------------------------------
// att[n] = dinv[n]*(p2[n] + q2[n]) + b2
// Single block: k = count(y>=0); cutoff = k-th largest of att[:S]; loss.
__global__ void k_select(const int* __restrict__ y, const float* __restrict__ b2,
                         float* __restrict__ out, int write_loss) {
    __shared__ float s_val[SDIM];
    __shared__ float s_t[SDIM];
    __shared__ int   s_k;
    __shared__ float s_rv[32];
    __shared__ int   s_ri[32];
    __shared__ float s_cut;
    int tid = threadIdx.x;
    if (tid == 0) s_k = 0;
    float bb = b2[0];
    for (int i = tid; i < SDIM; i += 1024) {
        float a = g_dinv[i] * (g_p2[i] + g_q2[i]) + bb;
        s_val[i] = a;
        g_att_s[i] = a;           // exact bits reused by k_mask
        s_t[i] = 0.f;
    }
    __syncthreads();

    int kc = 0;
    for (int j = tid; j < SDIM; j += 1024) {
        int yy = y[j];
        kc += (yy >= 0);
        if (yy > 0) s_t[yy] = 1.0f;   // idempotent; races benign
    }
    #pragma unroll
    for (int o = 16; o; o >>= 1) kc += __shfl_xor_sync(0xffffffffu, kc, o);
    if ((tid & 31) == 0) atomicAdd(&s_k, kc);
    __syncthreads();
    int k = max(s_k, 1);

    // per-thread loss accumulation BEFORE destructive selection
    float acc = 0.f;
    for (int j = tid; j < SDIM; j += 1024) {
        float v = s_val[j], t = s_t[j];
        float lp = log1pf(expf(-fabsf(v)));
        acc += t * (fminf(v, 0.f) - lp) + (1.f - t) * (fminf(-v, 0.f) - lp);
    }

    // k iterative (val, idx) argmax reductions; remove one instance each round
    for (int it = 0; it < k; it++) {
        float bv = -3.4e38f;
        int   bi = SDIM;
        for (int j = tid; j < SDIM; j += 1024) {
            float v = s_val[j];
            if (v > bv) { bv = v; bi = j; }
        }
        #pragma unroll
        for (int o = 16; o; o >>= 1) {
            float ov = __shfl_xor_sync(0xffffffffu, bv, o);
            int   oi = __shfl_xor_sync(0xffffffffu, bi, o);
            if (ov > bv || (ov == bv && oi < bi)) { bv = ov; bi = oi; }
        }
        if ((tid & 31) == 0) { s_rv[tid >> 5] = bv; s_ri[tid >> 5] = bi; }
        __syncthreads();
        if (tid < 32) {
            bv = s_rv[tid]; bi = s_ri[tid];
            #pragma unroll
            for (int o = 16; o; o >>= 1) {
                float ov = __shfl_xor_sync(0xffffffffu, bv, o);
                int   oi = __shfl_xor_sync(0xffffffffu, bi, o);
                if (ov > bv || (ov == bv && oi < bi)) { bv = ov; bi = oi; }
            }
            if (tid == 0) { s_cut = bv; s_val[bi] = -3.4e38f; }
        }
        __syncthreads();
    }
    if (tid == 0) g_cutoff = s_cut;

    // loss reduction
    #pragma unroll
    for (int o = 16; o; o >>= 1) acc += __shfl_xor_sync(0xffffffffu, acc, o);
    if ((tid & 31) == 0) s_rv[tid >> 5] = acc;
    __syncthreads();
    if (tid == 0 && write_loss) {
        float tot = 0.f;
        #pragma unroll
        for (int w = 0; w < 32; w++) tot += s_rv[w];
        out[0] = -tot / (float)SDIM;
    }
}

// ---------------------------------------------------------------------------
// mask; side work: re-zero g_deg so the next run (graph replay) starts clean
__global__ void k_mask(const float* __restrict__ b2, float* __restrict__ out, int off) {
    int n = blockIdx.x * blockDim.x + threadIdx.x;
    if (n >= N_NODES) return;
    float a;
    if (n < SDIM) {
        a = g_att_s[n];                      // identical bits to k_select
    } else {
        a = g_dinv[n] * (g_p2[n] + g_q2[n]) + b2[0];
    }
    out[off + n] = (a >= g_cutoff) ? 1.0f : 0.0f;
    g_deg[n] = 0.f;
}

// ---------------------------------------------------------------------------
extern "C" void kernel_launch(void* const* d_in, const int* in_sizes, int n_in,
                              void* d_out, int out_size) {
    const float* x  = (const float*)d_in[0];
    const int*   ei = (const int*)d_in[1];
    const float* ew = (const float*)d_in[2];
    const int*   y  = (const int*)d_in[3];
    const float* W1 = (const float*)d_in[4];
    const float* b1 = (const float*)d_in[5];
    const float* W2 = (const float*)d_in[6];
    const float* b2 = (const float*)d_in[7];
    const int* row = ei;             // edge_index[0,:]
    const int* col = ei + N_EDGES;   // edge_index[1,:]
    float* out = (float*)d_out;
    int off = (out_size > N_NODES) ? (out_size - N_NODES) : 0;  // expect 1

    k_vdeg<<<VB + EB4, 256>>>(W1, W2, b1, col, ew);
    k_z<<<(N_NODES + 7) / 8, 256>>>(x);
    k_edge1<<<EB2, 256>>>(row, col, ew);
    k_mid<<<NB, 256>>>();
    k_edge2<<<EB2, 256>>>(row, col, ew);
    k_select<<<1, 1024>>>(y, b2, out, off >= 1 ? 1 : 0);
    k_mask<<<NB, 256>>>(b2, out, off);
}